// round 12
// baseline (speedup 1.0000x reference)
#include <cuda_runtime.h>

#define B 64
#define H 768
#define E 128

#define NRED 256    // core-reduce blocks (32 KB each), bids [0,256)
#define KS 12       // GEMM k-splits
#define NGEMM 192   // 12 ks x 8 echunk x 2 bgroup, bids [256,448)
#define GRID (NRED + NGEMM)

__device__ float g_S2p[NRED];          // core partials (2 per leading index i)
__device__ float g_P[3][KS][B][E];     // [mat][ks][b][e] gemm partials

// ---------------------------------------------------------------------------
// Kernel A (R2-proven): blocks [0,256) reduce core (MLP=8);
// blocks [256,448) triple GEMM 32b x 16e x 64k.
// Fires the PDL trigger at entry so the combine kernel's launch overhead
// overlaps with this kernel's execution.
// ---------------------------------------------------------------------------
__global__ void k_fused(const float* __restrict__ core,
                        const float* __restrict__ hs, const float* __restrict__ rs,
                        const float* __restrict__ ts, const float* __restrict__ we,
                        const float* __restrict__ wr) {
    asm volatile("griddepcontrol.launch_dependents;");

    __shared__ float4 s_src[3][32][18];  // gemm src tiles (swizzled)
    __shared__ float4 s_w[2][16][18];    // gemm We/Wr tiles

    const int bid = blockIdx.x;
    const int tid = threadIdx.x;

    if (bid < NRED) {
        const float4* src = reinterpret_cast<const float4*>(core) + (size_t)bid * 2048;
        const float4 v0 = __ldg(src + tid);
        const float4 v1 = __ldg(src + tid + 256);
        const float4 v2 = __ldg(src + tid + 512);
        const float4 v3 = __ldg(src + tid + 768);
        const float4 v4 = __ldg(src + tid + 1024);
        const float4 v5 = __ldg(src + tid + 1280);
        const float4 v6 = __ldg(src + tid + 1536);
        const float4 v7 = __ldg(src + tid + 1792);
        float s = ((((v0.x + v0.y) + (v0.z + v0.w)) + ((v1.x + v1.y) + (v1.z + v1.w)))
                +  (((v2.x + v2.y) + (v2.z + v2.w)) + ((v3.x + v3.y) + (v3.z + v3.w))))
                + ((((v4.x + v4.y) + (v4.z + v4.w)) + ((v5.x + v5.y) + (v5.z + v5.w)))
                +  (((v6.x + v6.y) + (v6.z + v6.w)) + ((v7.x + v7.y) + (v7.z + v7.w))));
#pragma unroll
        for (int o = 16; o > 0; o >>= 1) s += __shfl_xor_sync(0xffffffffu, s, o);
        float* ws = reinterpret_cast<float*>(s_w);
        if ((tid & 31) == 0) ws[tid >> 5] = s;
        __syncthreads();
        if (tid == 0) {
            float tot = 0.f;
#pragma unroll
            for (int w = 0; w < 8; w++) tot += ws[w];
            g_S2p[bid] = tot;
        }
        return;
    }

    const int lin = bid - NRED;
    const int ks = lin % KS, ec = (lin / KS) & 7, bg = lin / (KS * 8);
    const int b0 = bg * 32, e0 = ec * 16;
    const int c0 = ks * 16;

    const float4* g0 = reinterpret_cast<const float4*>(hs);
    const float4* g1 = reinterpret_cast<const float4*>(rs);
    const float4* g2 = reinterpret_cast<const float4*>(ts);
#pragma unroll
    for (int i = tid; i < 512; i += 256) {
        const int row = i >> 4, c4 = i & 15;
        const size_t gidx = (size_t)(b0 + row) * 192 + c0 + c4;
        const int sc = c4 ^ (row & 7);
        s_src[0][row][sc] = g0[gidx];
        s_src[1][row][sc] = g1[gidx];
        s_src[2][row][sc] = g2[gidx];
    }
    {
        const int row = tid >> 4, c4 = tid & 15;
        const size_t gidx = (size_t)(e0 + row) * 192 + c0 + c4;
        const int sc = c4 ^ (row & 7);
        s_w[0][row][sc] = reinterpret_cast<const float4*>(we)[gidx];
        s_w[1][row][sc] = reinterpret_cast<const float4*>(wr)[gidx];
    }
    __syncthreads();

    const int te = tid & 15;
    const int tb = tid >> 4;
    const int ba = 2 * tb, bb = ba + 1;

    float h0 = 0.f, h1 = 0.f, r0 = 0.f, r1 = 0.f, t0 = 0.f, t1 = 0.f;
#pragma unroll
    for (int k4 = 0; k4 < 16; k4++) {
        const float4 vwe = s_w[0][te][k4 ^ (te & 7)];
        const float4 vwr = s_w[1][te][k4 ^ (te & 7)];
        const int sa = k4 ^ (ba & 7), sb = k4 ^ (bb & 7);
        float4 a, c;
        a = s_src[0][ba][sa]; c = s_src[0][bb][sb];
        h0 += vwe.x * a.x + vwe.y * a.y + vwe.z * a.z + vwe.w * a.w;
        h1 += vwe.x * c.x + vwe.y * c.y + vwe.z * c.z + vwe.w * c.w;
        a = s_src[1][ba][sa]; c = s_src[1][bb][sb];
        r0 += vwr.x * a.x + vwr.y * a.y + vwr.z * a.z + vwr.w * a.w;
        r1 += vwr.x * c.x + vwr.y * c.y + vwr.z * c.z + vwr.w * c.w;
        a = s_src[2][ba][sa]; c = s_src[2][bb][sb];
        t0 += vwe.x * a.x + vwe.y * a.y + vwe.z * a.z + vwe.w * a.w;
        t1 += vwe.x * c.x + vwe.y * c.y + vwe.z * c.z + vwe.w * c.w;
    }

    const int bga = b0 + ba, bgb = b0 + bb;
    const int e = e0 + te;
    g_P[0][ks][bga][e] = h0;  g_P[0][ks][bgb][e] = h1;
    g_P[1][ks][bga][e] = r0;  g_P[1][ks][bgb][e] = r1;
    g_P[2][ks][bga][e] = t0;  g_P[2][ks][bgb][e] = t1;
}

// ---------------------------------------------------------------------------
// Kernel B: PDL secondary. Parks at griddepcontrol.wait (hardware wait with
// full memory-visibility guarantee for the primary's stores), then combines.
// 64 blocks x 384 threads; thread (m,e) sums 12 ks partials (MLP=12).
// ---------------------------------------------------------------------------
__global__ void k_combine(const float* __restrict__ be, const float* __restrict__ br,
                          float* __restrict__ out) {
    asm volatile("griddepcontrol.wait;" ::: "memory");

    __shared__ float sh[3][128];
    __shared__ float sred[4];

    const int b = blockIdx.x;
    const int tid = threadIdx.x;           // 0..383
    const int m = tid >> 7;                // matrix 0/1/2
    const int e = tid & 127;

    const float* p = &g_P[m][0][b][e];     // stride between ks = B*E floats
    float s = 0.f;
#pragma unroll
    for (int k = 0; k < KS; k++) s += __ldg(p + (size_t)k * (B * E));
    sh[m][e] = s;
    __syncthreads();

    if (tid < 128) {
        const float bias_e = be[tid], bias_r = br[tid];
        const float h = sh[0][tid] + bias_e;
        const float r = sh[1][tid] + bias_r;
        const float t = sh[2][tid] + bias_e;
        const float s2 = g_S2p[2 * tid] + g_S2p[2 * tid + 1];
        float v = h * r * t * s2;
#pragma unroll
        for (int o = 16; o > 0; o >>= 1) v += __shfl_xor_sync(0xffffffffu, v, o);
        if ((tid & 31) == 0) sred[tid >> 5] = v;
    }
    __syncthreads();
    if (tid == 0) out[b] = -((sred[0] + sred[1]) + (sred[2] + sred[3]));
}

// ---------------------------------------------------------------------------
extern "C" void kernel_launch(void* const* d_in, const int* in_sizes, int n_in,
                              void* d_out, int out_size) {
    const float* head = (const float*)d_in[0];
    const float* rel  = (const float*)d_in[1];
    const float* tail = (const float*)d_in[2];
    const float* We   = (const float*)d_in[3];
    const float* be   = (const float*)d_in[4];
    const float* Wr   = (const float*)d_in[5];
    const float* br   = (const float*)d_in[6];
    const float* core = (const float*)d_in[7];
    float* out = (float*)d_out;

    k_fused<<<GRID, 256>>>(core, head, rel, tail, We, Wr);

    // Combine as a programmatic dependent launch: its launch/dispatch overhead
    // overlaps with k_fused execution; blocks wait at griddepcontrol.wait.
    cudaLaunchConfig_t cfg = {};
    cfg.gridDim = dim3(B);
    cfg.blockDim = dim3(384);
    cfg.dynamicSmemBytes = 0;
    cfg.stream = 0;
    cudaLaunchAttribute attr[1];
    attr[0].id = cudaLaunchAttributeProgrammaticStreamSerialization;
    attr[0].val.programmaticStreamSerializationAllowed = 1;
    cfg.attrs = attr;
    cfg.numAttrs = 1;
    cudaLaunchKernelEx(&cfg, k_combine, be, br, out);
}